// round 15
// baseline (speedup 1.0000x reference)
#include <cuda_runtime.h>
#include <cuda_bf16.h>

#define NN     16384
#define GRID   64
#define NT     512
#define NBK    64            // rank buckets: bucket = rank >> 8
#define NBIN   2048          // value bins per bucket
#define CAP    512           // per-bucket capacity (mean 256, sd 16)
#define PADI   32            // ints per 128B line (counter stride)
#define TLO    (-8.0f)
#define TINV   (128.0f)      // 1/step, step = 1/128, range [-8, 8)

// ------------- device scratch (zero-init at load; re-zeroed per launch) -------
__device__ __align__(16) float  g_bsc[NBK * CAP];   // bucket scores
__device__ __align__(16) int    g_brk[NBK * CAP];   // bucket ranks
__device__ __align__(16) float  g_hcnt[NBK * NBIN]; // hist counts (zeroed in P2)
__device__ __align__(16) float  g_hsum[NBK * NBIN]; // hist sums   (zeroed in P2)
__device__ __align__(16) float2 g_tab[NBK * NBIN];  // per-bucket CDF (cnt>=, sum>=)
__device__ __align__(16) float2 g_stab[NBK * NBIN]; // S[rb] = sum_{c>rb} cdf_c
__device__ __align__(128) int   g_bcnt[NBK * PADI]; // padded counters
__device__ double               g_part[GRID];
__device__ long long            g_tiedp[GRID];
__device__ unsigned             g_done;
__device__ unsigned             g_barc;             // monotonic barrier ticket

__device__ __forceinline__ float2 add2(float2 a, float2 b) {
    return make_float2(a.x + b.x, a.y + b.y);
}
__device__ __forceinline__ float2 shfl_down2(float2 v, int o) {
    v.x = __shfl_down_sync(0xffffffffu, v.x, o);
    v.y = __shfl_down_sync(0xffffffffu, v.y, o);
    return v;
}

// Replay-safe grid barrier: monotonic ticket; 3 barriers x 64 arrivals per
// launch keeps the counter = 0 mod GRID.  All 64 blocks co-resident (<=148 SMs).
__device__ __forceinline__ void gbar(int tid) {
    __threadfence();
    __syncthreads();
    if (tid == 0) {
        unsigned t = atomicAdd(&g_barc, 1u);
        unsigned target = (t / GRID + 1u) * GRID;
        while (*(volatile unsigned*)&g_barc < target) { }
    }
    __syncthreads();
}

extern "C" __global__ void __launch_bounds__(NT, 1)
k_all(const float* __restrict__ scores, const unsigned int* __restrict__ rw,
      float* __restrict__ out)
{
    __shared__ int    hcnt[NBK], hbase[NBK];
    __shared__ float2 wt2[16];
    __shared__ float  sda[CAP];
    __shared__ int    sdr[CAP];
    __shared__ double wsd[2];
    __shared__ long long wst[2];
    __shared__ int    s_flag;
    const int tid = threadIdx.x, b = blockIdx.x;
    const int lane = tid & 31, wid = tid >> 5;

    // ---------------- P1: scatter + histogram ----------------
    // dtype self-detect: int64 (LE) -> odd 32-bit words of this block's window
    // are high halves of values < 2^15 -> all zero.  int32 -> actual ranks.
    if (tid < NBK) hcnt[tid] = 0;
    int found = 0;
    if (tid < 128) found = (rw[b * 256 + 2 * tid + 1] != 0u);
    int is32 = __syncthreads_or(found);          // also orders hcnt zeroing

    float sv = 0.0f; int rv = 0, kb = 0, lpos = 0;
    if (tid < 256) {
        int i = b * 256 + tid;
        sv = scores[i];
        rv = (int)rw[is32 ? i : 2 * i];
        if ((unsigned)rv >= (unsigned)NN) rv = 0; // defensive: never IMA
        kb = rv >> 8;
        int bin = (int)floorf((sv - TLO) * TINV);
        bin = max(0, min(bin, NBIN - 1));
        atomicAdd(&g_hcnt[kb * NBIN + bin], 1.0f);   // fire-and-forget REDs
        atomicAdd(&g_hsum[kb * NBIN + bin], sv);
        lpos = atomicAdd(&hcnt[kb], 1);              // smem atomic
    }
    __syncthreads();
    if (tid < NBK)
        hbase[tid] = atomicAdd(&g_bcnt[tid * PADI], hcnt[tid]);
    __syncthreads();
    if (tid < 256) {
        int pos = hbase[kb] + lpos;
        if (pos < CAP) {
            g_bsc[kb * CAP + pos] = sv;
            g_brk[kb * CAP + pos] = rv;
        }
    }
    gbar(tid);

    // ---------------- P2: bin-suffix CDF for bucket b + zero hist ----------
    {
        int base = b * NBIN + tid * 4;
        float4 hc = *(const float4*)&g_hcnt[base];
        float4 hs = *(const float4*)&g_hsum[base];
        float4 z4 = make_float4(0.f, 0.f, 0.f, 0.f);
        *(float4*)&g_hcnt[base] = z4;             // re-zero for next replay
        *(float4*)&g_hsum[base] = z4;
        float2 v0 = make_float2(hc.x, hs.x), v1 = make_float2(hc.y, hs.y);
        float2 v2 = make_float2(hc.z, hs.z), v3 = make_float2(hc.w, hs.w);
        float2 y3 = v3, y2 = add2(v2, y3), y1 = add2(v1, y2), y0 = add2(v0, y1);
        float2 tot = y0;
        float2 sfx = tot;                          // warp inclusive suffix
#pragma unroll
        for (int o = 1; o < 32; o <<= 1) {
            float2 n = shfl_down2(sfx, o);
            if (lane + o < 32) sfx = add2(sfx, n);
        }
        if (lane == 0) wt2[wid] = sfx;             // warp totals
        __syncthreads();
        if (wid == 0) {
            float2 t = (lane < 16) ? wt2[lane] : make_float2(0.f, 0.f);
#pragma unroll
            for (int o = 1; o < 16; o <<= 1) {
                float2 n = shfl_down2(t, o);
                if (lane + o < 32) t = add2(t, n);
            }
            if (lane < 16) wt2[lane] = t;          // inclusive suffix of totals
        }
        __syncthreads();
        float2 beyond = (wid < 15) ? wt2[wid + 1] : make_float2(0.f, 0.f);
        float2 e = make_float2(sfx.x - tot.x + beyond.x,
                               sfx.y - tot.y + beyond.y);
        g_tab[base + 0] = add2(y0, e);
        g_tab[base + 1] = add2(y1, e);
        g_tab[base + 2] = add2(y2, e);
        g_tab[base + 3] = add2(y3, e);
    }
    gbar(tid);

    // ---------------- P2.5: bucket-suffix S[c][bin] = sum_{c'>c} cdf ----------
    if (tid < 32) {
        int bin = b * 32 + tid;                    // coalesced per warp
        float2 run = make_float2(0.f, 0.f);
#pragma unroll 16
        for (int c = NBK - 1; c >= 0; c--) {
            float2 v = g_tab[c * NBIN + bin];
            g_stab[c * NBIN + bin] = run;          // strictly-greater buckets
            run = add2(run, v);
        }
    }
    gbar(tid);

    // ---------------- P3: one lookup per element + exact diag ----------------
    int cnt = min(g_bcnt[b * PADI], CAP);
    sda[tid] = g_bsc[b * CAP + tid];
    sdr[tid] = g_brk[b * CAP + tid];
    __syncthreads();
    float facc = 0.0f;
    long long ltied = 0;
    if (tid < cnt) {
        float s = sda[tid];
        int ri = sdr[tid];
        float ap = 1.0f - s;
        int q = (int)floorf((s - 1.0f - TLO) * TINV) + 1;
        q = max(0, min(q, NBIN - 1));
        float2 cs = g_stab[b * NBIN + q];          // cross: ONE lookup
        facc = fmaf(cs.x, ap, cs.y);
        for (int j = 0; j < cnt; j++) {            // diag: exact rank compare
            int rj = sdr[j];
            if (rj > ri)                   facc += fmaxf(ap + sda[j], 0.0f);
            else if (rj == ri && j > tid)  ltied++;
        }
    }

    // block reduce -> per-block slots (no atomics), then done-ticket
#pragma unroll
    for (int o = 16; o; o >>= 1) {
        facc  += __shfl_down_sync(0xffffffffu, facc, o);
        ltied += __shfl_down_sync(0xffffffffu, ltied, o);
    }
    {
        __shared__ float wv[16];
        __shared__ long long wl[16];
        if (lane == 0) { wv[wid] = facc; wl[wid] = ltied; }
        __syncthreads();
        if (tid == 0) {
            float sf = 0.0f; long long sl = 0;
#pragma unroll
            for (int u = 0; u < 16; u++) { sf += wv[u]; sl += wl[u]; }
            g_part[b]  = (double)sf;
            g_tiedp[b] = sl;
            g_bcnt[b * PADI] = 0;                  // re-zero own counter
            __threadfence();
            unsigned d = atomicAdd(&g_done, 1u);
            s_flag = (d == (unsigned)(GRID - 1)) ? 1 : 0;
        }
        __syncthreads();
    }

    // last-done block finalizes (all 512 threads alive here)
    if (s_flag) {
        double v = (tid < GRID) ? g_part[tid] : 0.0;
        long long tv = (tid < GRID) ? g_tiedp[tid] : 0;
#pragma unroll
        for (int o = 16; o; o >>= 1) {
            v  += __shfl_down_sync(0xffffffffu, v, o);
            tv += __shfl_down_sync(0xffffffffu, tv, o);
        }
        if (tid < 64 && lane == 0) { wsd[wid] = v; wst[wid] = tv; }
        __syncthreads();
        if (tid == 0) {
            double s = wsd[0] + wsd[1];
            long long tt = wst[0] + wst[1];
            double np = (double)(134209536ll - tt);   // C(16384,2) - tied
            out[0] = (np > 0.0) ? (float)(s / np) : 0.0f;
            g_done = 0u;                              // reset for next replay
        }
    }
}

// ---------------- launch: ONE kernel ----------------
extern "C" void kernel_launch(void* const* d_in, const int* in_sizes, int n_in,
                              void* d_out, int out_size) {
    const float*        scores = (const float*)d_in[0];
    const unsigned int* ranks  = (const unsigned int*)d_in[1];
    float* out = (float*)d_out;

    k_all<<<GRID, NT>>>(scores, ranks, out);
}